// round 7
// baseline (speedup 1.0000x reference)
#include <cuda_runtime.h>
#include <cstdint>

#define B_  64
#define N_  256
#define H_  1024
#define NK_ 768     // N*K, K=3

// Device-global scratch (the sanctioned no-allocation workaround).
// All GEMM operands are pre-converted ONCE to tf32 bit patterns:
//   tf32 register format == fp32 layout, low 13 mantissa bits ignored by MMA,
//   so pre-converting with cvt.rna is numerically identical to converting at
//   every fragment load (as previous revisions did) — just cheaper.
__device__ uint32_t g_weight[(size_t)B_ * N_ * NK_];   // gemm1 out / gemm2 A (48 MB)
__device__ uint32_t g_f [(size_t)B_ * N_ * H_];        // f  as tf32 bits (64 MB)
__device__ uint32_t g_k [(size_t)B_ * N_ * H_];        // k  as tf32 bits (64 MB)
__device__ uint32_t g_wl[(size_t)NK_ * H_];            // W_lin as tf32 bits (3 MB)

__device__ __forceinline__ uint32_t f2tf(float x) {
    uint32_t r;
    asm("cvt.rna.tf32.f32 %0, %1;" : "=r"(r) : "f"(x));
    return r;
}

__device__ __forceinline__ void mma8(float* c, const uint32_t* a, const uint32_t* b) {
    asm volatile(
        "mma.sync.aligned.m16n8k8.row.col.f32.tf32.tf32.f32 "
        "{%0,%1,%2,%3}, {%4,%5,%6,%7}, {%8,%9}, {%0,%1,%2,%3};\n"
        : "+f"(c[0]), "+f"(c[1]), "+f"(c[2]), "+f"(c[3])
        : "r"(a[0]), "r"(a[1]), "r"(a[2]), "r"(a[3]), "r"(b[0]), "r"(b[1]));
}

__device__ __forceinline__ void cpa16(uint32_t dst, const void* src) {
    asm volatile("cp.async.cg.shared.global [%0], [%1], 16;\n"
                 :: "r"(dst), "l"(src) : "memory");
}
// 4-byte copy with zero-fill when pred is off. src is always a VALID address
// (clamped by caller); src-size=0 selects the zero-fill path.
__device__ __forceinline__ void cpa4z(uint32_t dst, const void* src, int srcsz) {
    asm volatile("cp.async.ca.shared.global [%0], [%1], 4, %2;\n"
                 :: "r"(dst), "l"(src), "r"(srcsz) : "memory");
}
#define CP_COMMIT() asm volatile("cp.async.commit_group;\n" ::: "memory")
#define CP_WAIT1()  asm volatile("cp.async.wait_group 1;\n" ::: "memory")

// ---------------------------------------------------------------------------
// Pre-pass: elementwise fp32 -> tf32 bits (grid-stride, float4/uint4).
// Bandwidth-bound; ~33 us for all three arrays combined.
// ---------------------------------------------------------------------------
__global__ void cvt_kernel(const float* __restrict__ src,
                           uint32_t* __restrict__ dst, int n4) {
    int i = blockIdx.x * blockDim.x + threadIdx.x;
    int stride = gridDim.x * blockDim.x;
    for (; i < n4; i += stride) {
        float4 v = ((const float4*)src)[i];
        uint4 o;
        o.x = f2tf(v.x); o.y = f2tf(v.y); o.z = f2tf(v.z); o.w = f2tf(v.w);
        ((uint4*)dst)[i] = o;
    }
}

// ---------------------------------------------------------------------------
// GEMM1: weight[(b,n)][o] = f[(b,n)][:1024] . W_lin[o][:1024] + b_lin[o]
// M=16384, N=768, K=1024. Block tile 128x128, BK=32, 8 warps (4x2),
// warp tile 32x64 (2x8 m16n8k8). Operands read as PRE-CONVERTED tf32 bits;
// no cvt in the hot loop. 3-stage cp.async pipeline, ONE barrier per tile
// (prologue fills 2 stages; iter t: wait_group(1), sync, compute stage t%3,
// issue tile t+2 into stage (t+2)%3 — reader-free after the sync — commit).
// Smem stride 36 (conflict-free for cp.async stores and fragment LDS).
// ---------------------------------------------------------------------------
#define G1_TILE   (128 * 36)                // words per stage per operand
#define G1_SMEM   (6 * G1_TILE * 4)         // bytes: As[3] + Bs[3] = 110592

__global__ __launch_bounds__(256, 2)
void gemm1_kernel(const float* __restrict__ bl) {
    extern __shared__ uint32_t sm1[];
    uint32_t* Asb = sm1;                     // [3][G1_TILE]
    uint32_t* Bsb = sm1 + 3 * G1_TILE;       // [3][G1_TILE]
    const uint32_t s_as = (uint32_t)__cvta_generic_to_shared(Asb);
    const uint32_t s_bs = (uint32_t)__cvta_generic_to_shared(Bsb);

    const int tid  = threadIdx.x;
    const int m0   = blockIdx.y * 128;
    const int n0   = blockIdx.x * 128;
    const int warp = tid >> 5, lane = tid & 31;
    const int wm   = (warp >> 1) * 32;
    const int wn   = (warp & 1) * 64;
    const int gid  = lane >> 2, tig = lane & 3;
    const int lr   = tid >> 3;               // 0..31
    const int lc   = (tid & 7) * 4;          // 0..28

    float acc[2][8][4];
#pragma unroll
    for (int i = 0; i < 2; i++)
#pragma unroll
        for (int j = 0; j < 8; j++)
#pragma unroll
            for (int l = 0; l < 4; l++) acc[i][j][l] = 0.f;

    auto issue = [&](int t, int s) {
        const int kof = t * 32 + lc;
        const uint32_t da = s_as + (uint32_t)(s * G1_TILE + lr * 36 + lc) * 4;
        const uint32_t db = s_bs + (uint32_t)(s * G1_TILE + lr * 36 + lc) * 4;
#pragma unroll
        for (int it = 0; it < 4; it++) {
            int r = it * 32;
            cpa16(da + (uint32_t)(r * 36) * 4,
                  g_f  + (size_t)(m0 + lr + r) * H_ + kof);
            cpa16(db + (uint32_t)(r * 36) * 4,
                  g_wl + (size_t)(n0 + lr + r) * H_ + kof);
        }
    };

    const int T = H_ / 32;                   // 32 tiles
    issue(0, 0); CP_COMMIT();
    issue(1, 1); CP_COMMIT();

#pragma unroll 1
    for (int t = 0; t < T; t++) {
        CP_WAIT1();                          // tile t's group complete
        __syncthreads();                     // visible; prior stage readers done
        const int s = (t < 3) ? t : (t % 3);
        const uint32_t* Af = Asb + s * G1_TILE;
        const uint32_t* Bf = Bsb + s * G1_TILE;
#pragma unroll
        for (int ks = 0; ks < 4; ks++) {
            uint32_t af[2][4], bf[8][2];
#pragma unroll
            for (int mt = 0; mt < 2; mt++) {
                int row = wm + mt * 16 + gid;
                int col = ks * 8 + tig;
                af[mt][0] = Af[row * 36 + col];
                af[mt][1] = Af[(row + 8) * 36 + col];
                af[mt][2] = Af[row * 36 + col + 4];
                af[mt][3] = Af[(row + 8) * 36 + col + 4];
            }
#pragma unroll
            for (int nt = 0; nt < 8; nt++) {
                int nr = wn + nt * 8 + gid;
                bf[nt][0] = Bf[nr * 36 + ks * 8 + tig];
                bf[nt][1] = Bf[nr * 36 + ks * 8 + tig + 4];
            }
#pragma unroll
            for (int mt = 0; mt < 2; mt++)
#pragma unroll
                for (int nt = 0; nt < 8; nt++)
                    mma8(acc[mt][nt], af[mt], bf[nt]);
        }
        if (t + 2 < T) issue(t + 2, (t + 2) % 3);
        CP_COMMIT();                         // always commit: uniform accounting
    }

#pragma unroll
    for (int mt = 0; mt < 2; mt++) {
        int r = m0 + wm + mt * 16 + gid;
#pragma unroll
        for (int nt = 0; nt < 8; nt++) {
            int c = n0 + wn + nt * 8 + tig * 2;
            float2 bb = *(const float2*)(bl + c);
            uint2 w0, w1;
            w0.x = f2tf(acc[mt][nt][0] + bb.x);
            w0.y = f2tf(acc[mt][nt][1] + bb.y);
            w1.x = f2tf(acc[mt][nt][2] + bb.x);
            w1.y = f2tf(acc[mt][nt][3] + bb.y);
            *(uint2*)(g_weight + (size_t)r * NK_ + c) = w0;
            *(uint2*)(g_weight + (size_t)(r + 8) * NK_ + c) = w1;
        }
    }
}

// ---------------------------------------------------------------------------
// GEMM2 (dynamic conv): out[b,n,h] = sum_j weight[b,n,j]*kpad[b, j/3, h+(j%3)-1]
// A = g_weight[b] (tf32 bits). B gathered from g_k[b] (tf32 bits) via 4-byte
// cp.async with zero-fill at the +-1 SAME-pad boundary (source pointer clamped
// in-bounds when predicated off). No cvt in the hot loop. A smem stride 36,
// B smem [k=32][h=128] stride 136. Same 3-stage one-barrier pipeline.
// ---------------------------------------------------------------------------
#define G2_ATILE  (128 * 36)
#define G2_BTILE  (32 * 136)
#define G2_SMEM   (3 * (G2_ATILE + G2_BTILE) * 4)   // 107520 B

__global__ __launch_bounds__(256, 2)
void gemm2_kernel(float* __restrict__ Out) {
    extern __shared__ uint32_t sm2[];
    uint32_t* Asb = sm2;                         // [3][G2_ATILE]
    uint32_t* Bsb = sm2 + 3 * G2_ATILE;          // [3][G2_BTILE]
    const uint32_t s_as = (uint32_t)__cvta_generic_to_shared(Asb);
    const uint32_t s_bs = (uint32_t)__cvta_generic_to_shared(Bsb);

    const int tid = threadIdx.x;
    const int b   = blockIdx.z;
    const int m0  = blockIdx.y * 128;            // n dim: 0 or 128
    const int h0  = blockIdx.x * 128;            // 0..896
    const uint32_t* A  = g_weight + (size_t)b * N_ * NK_;
    const uint32_t* kb = g_k + (size_t)b * N_ * H_;

    const int warp = tid >> 5, lane = tid & 31;
    const int wm  = (warp >> 1) * 32;
    const int wn  = (warp & 1) * 64;
    const int gid = lane >> 2, tig = lane & 3;
    const int lr  = tid >> 3;
    const int lc  = (tid & 7) * 4;
    const int bh  = tid & 127;                   // h position
    const int bj0 = tid >> 7;                    // 0..1

    float acc[2][8][4];
#pragma unroll
    for (int i = 0; i < 2; i++)
#pragma unroll
        for (int j = 0; j < 8; j++)
#pragma unroll
            for (int l = 0; l < 4; l++) acc[i][j][l] = 0.f;

    auto issue = [&](int t, int s) {
        const int kof = t * 32 + lc;
        const uint32_t da = s_as + (uint32_t)(s * G2_ATILE + lr * 36 + lc) * 4;
#pragma unroll
        for (int it = 0; it < 4; it++) {
            int r = it * 32;
            cpa16(da + (uint32_t)(r * 36) * 4,
                  A + (size_t)(m0 + lr + r) * NK_ + kof);
        }
#pragma unroll
        for (int it = 0; it < 16; it++) {
            int jl = bj0 + it * 2;               // 0..31
            int jg = t * 32 + jl;
            int m  = jg / 3;
            int kk = jg - m * 3;
            int hx = h0 + bh + kk - 1;           // SAME pad shift
            bool in = (hx >= 0 && hx < H_);
            const uint32_t* src = in ? (kb + (size_t)m * H_ + hx) : kb; // clamped
            cpa4z(s_bs + (uint32_t)(s * G2_BTILE + jl * 136 + bh) * 4,
                  src, in ? 4 : 0);
        }
    };

    const int T = NK_ / 32;                      // 24 tiles
    issue(0, 0); CP_COMMIT();
    issue(1, 1); CP_COMMIT();

#pragma unroll 1
    for (int t = 0; t < T; t++) {
        CP_WAIT1();
        __syncthreads();
        const int s = (t < 3) ? t : (t % 3);
        const uint32_t* Ab = Asb + s * G2_ATILE;
        const uint32_t* Bf = Bsb + s * G2_BTILE;
#pragma unroll
        for (int ks = 0; ks < 4; ks++) {
            uint32_t af[2][4], bf[8][2];
#pragma unroll
            for (int mt = 0; mt < 2; mt++) {
                int row = wm + mt * 16 + gid;
                int col = ks * 8 + tig;
                af[mt][0] = Ab[row * 36 + col];
                af[mt][1] = Ab[(row + 8) * 36 + col];
                af[mt][2] = Ab[row * 36 + col + 4];
                af[mt][3] = Ab[(row + 8) * 36 + col + 4];
            }
#pragma unroll
            for (int nt = 0; nt < 8; nt++) {
                int nc = wn + nt * 8 + gid;
                bf[nt][0] = Bf[(ks * 8 + tig) * 136 + nc];
                bf[nt][1] = Bf[(ks * 8 + tig + 4) * 136 + nc];
            }
#pragma unroll
            for (int mt = 0; mt < 2; mt++)
#pragma unroll
                for (int nt = 0; nt < 8; nt++)
                    mma8(acc[mt][nt], af[mt], bf[nt]);
        }
        if (t + 2 < T) issue(t + 2, (t + 2) % 3);
        CP_COMMIT();
    }

#pragma unroll
    for (int mt = 0; mt < 2; mt++) {
        int r = m0 + wm + mt * 16 + gid;
        size_t rb = ((size_t)b * N_ + r) * H_;
#pragma unroll
        for (int nt = 0; nt < 8; nt++) {
            int c = h0 + wn + nt * 8 + tig * 2;
            *(float2*)(Out + rb + c) = make_float2(acc[mt][nt][0], acc[mt][nt][1]);
            *(float2*)(Out + rb + 8 * (size_t)H_ + c) =
                make_float2(acc[mt][nt][2], acc[mt][nt][3]);
        }
    }
}

// ---------------------------------------------------------------------------
// LayerNorm over H (in-place on d_out). One block per (b,n) row.
// ---------------------------------------------------------------------------
__global__ __launch_bounds__(256)
void ln_kernel(float* __restrict__ Out, const float* __restrict__ gamma,
               const float* __restrict__ beta) {
    __shared__ float red[8][2];
    const size_t row = blockIdx.x;
    float4* xp = (float4*)(Out + row * H_);
    float4 v = xp[threadIdx.x];
    float s = v.x + v.y + v.z + v.w;
    float q = v.x * v.x + v.y * v.y + v.z * v.z + v.w * v.w;
#pragma unroll
    for (int o = 16; o; o >>= 1) {
        s += __shfl_xor_sync(0xffffffffu, s, o);
        q += __shfl_xor_sync(0xffffffffu, q, o);
    }
    int warp = threadIdx.x >> 5, lane = threadIdx.x & 31;
    if (lane == 0) { red[warp][0] = s; red[warp][1] = q; }
    __syncthreads();
    s = 0.f; q = 0.f;
#pragma unroll
    for (int i = 0; i < 8; i++) { s += red[i][0]; q += red[i][1]; }
    float mu  = s * (1.f / H_);
    float var = q * (1.f / H_) - mu * mu;
    float inv = rsqrtf(var + 1e-5f);
    float4 g = ((const float4*)gamma)[threadIdx.x];
    float4 t = ((const float4*)beta)[threadIdx.x];
    v.x = (v.x - mu) * inv * g.x + t.x;
    v.y = (v.y - mu) * inv * g.y + t.y;
    v.z = (v.z - mu) * inv * g.z + t.z;
    v.w = (v.w - mu) * inv * g.w + t.w;
    xp[threadIdx.x] = v;
}

extern "C" void kernel_launch(void* const* d_in, const int* in_sizes, int n_in,
                              void* d_out, int out_size) {
    const float* f     = (const float*)d_in[0];
    const float* k     = (const float*)d_in[1];
    const float* Wl    = (const float*)d_in[2];
    const float* bl    = (const float*)d_in[3];
    const float* gamma = (const float*)d_in[4];
    const float* beta  = (const float*)d_in[5];
    float* out = (float*)d_out;

    // Idempotent; executed on the uncaptured correctness call first, so the
    // attribute is in place before graph capture.
    cudaFuncSetAttribute(gemm1_kernel,
                         cudaFuncAttributeMaxDynamicSharedMemorySize, G1_SMEM);
    cudaFuncSetAttribute(gemm2_kernel,
                         cudaFuncAttributeMaxDynamicSharedMemorySize, G2_SMEM);

    uint32_t *d_gf, *d_gk, *d_gwl;
    cudaGetSymbolAddress((void**)&d_gf,  g_f);
    cudaGetSymbolAddress((void**)&d_gk,  g_k);
    cudaGetSymbolAddress((void**)&d_gwl, g_wl);

    // Pre-pass: one-shot tf32 conversion of all GEMM operands.
    cvt_kernel<<<4096, 256>>>(f,  d_gf,  (B_ * N_ * H_) / 4);
    cvt_kernel<<<4096, 256>>>(k,  d_gk,  (B_ * N_ * H_) / 4);
    cvt_kernel<<<1024, 256>>>(Wl, d_gwl, (NK_ * H_) / 4);

    gemm1_kernel<<<dim3(6, 128), 256, G1_SMEM>>>(bl);
    gemm2_kernel<<<dim3(8, 2, 64), 256, G2_SMEM>>>(out);
    ln_kernel<<<B_ * N_, 256>>>(out, gamma, beta);
}